// round 1
// baseline (speedup 1.0000x reference)
#include <cuda_runtime.h>
#include <math_constants.h>

// Problem constants (FeatureAttention: N=500000, C=256, R=4, B=1024)
#define BSEG 1024
#define CCH  256
#define C4   64      // C/4 float4s per row
#define HID  64      // C/R

// Scratch (no dynamic allocation allowed)
__device__ int g_seg_start[BSEG + 1];
__device__ __align__(16) float g_y[BSEG * CCH];

// batch may arrive as int32 (JAX x64-off canonicalization) or int64 (as declared).
// Sorted, values in [0,1024). If int64 (little-endian), slot [n-1] (odd index) is a
// zero high-word; if int32, slot [n-1] is the max segment id (1023 w.p. ~1).
__device__ __forceinline__ int load_batch(const int* __restrict__ b32, bool is64, int i) {
    return is64 ? b32[2 * i] : b32[i];
}

// ---------------------------------------------------------------------------
// Kernel 1: segment boundaries via per-segment lower_bound (sorted batch).
// ---------------------------------------------------------------------------
__global__ void seg_bounds_kernel(const int* __restrict__ b32, int n) {
    int b = blockIdx.x * blockDim.x + threadIdx.x;
    if (b > BSEG) return;
    bool is64 = (b32[n - 1] == 0);
    int lo = 0, hi = n;
    while (lo < hi) {
        int mid = (lo + hi) >> 1;
        int v = load_batch(b32, is64, mid);
        if (v < b) lo = mid + 1; else hi = mid;
    }
    g_seg_start[b] = lo;
}

// ---------------------------------------------------------------------------
// Kernel 2: per-segment sum+max reduction, fused with the bottleneck MLP.
// One CTA per segment, 256 threads = 64 float4 lanes x 4 row-groups.
// y[b] = relu( (relu(sum@w1) + relu(max@w1)) @ w2 )   (w2 is linear)
// ---------------------------------------------------------------------------
__global__ void __launch_bounds__(256) seg_reduce_mlp_kernel(
    const float4* __restrict__ x4,
    const float*  __restrict__ w1,   // [C, H] row-major
    const float*  __restrict__ w2)   // [H, C] row-major
{
    __shared__ __align__(16) float4 rs[4][C4];
    __shared__ __align__(16) float4 rm[4][C4];
    __shared__ __align__(16) float  s_sum[CCH];
    __shared__ __align__(16) float  s_max[CCH];
    __shared__ float s_h[2 * HID];

    const int b   = blockIdx.x;
    const int tid = threadIdx.x;
    const int c4  = tid & 63;
    const int rg  = tid >> 6;

    const int start = g_seg_start[b];
    const int end   = g_seg_start[b + 1];

    float4 s = make_float4(0.f, 0.f, 0.f, 0.f);
    float4 m = make_float4(-CUDART_INF_F, -CUDART_INF_F, -CUDART_INF_F, -CUDART_INF_F);

    for (int r = start + rg; r < end; r += 4) {
        float4 v = x4[r * C4 + c4];
        s.x += v.x; s.y += v.y; s.z += v.z; s.w += v.w;
        m.x = fmaxf(m.x, v.x); m.y = fmaxf(m.y, v.y);
        m.z = fmaxf(m.z, v.z); m.w = fmaxf(m.w, v.w);
    }
    rs[rg][c4] = s;
    rm[rg][c4] = m;
    __syncthreads();

    if (rg == 0) {
        float4 a  = rs[0][c4];
        float4 mm = rm[0][c4];
        #pragma unroll
        for (int g = 1; g < 4; g++) {
            float4 t = rs[g][c4];
            a.x += t.x; a.y += t.y; a.z += t.z; a.w += t.w;
            float4 u = rm[g][c4];
            mm.x = fmaxf(mm.x, u.x); mm.y = fmaxf(mm.y, u.y);
            mm.z = fmaxf(mm.z, u.z); mm.w = fmaxf(mm.w, u.w);
        }
        if (end == start) mm = make_float4(0.f, 0.f, 0.f, 0.f);  // empty segment -> 0 (torch_scatter semantics)
        reinterpret_cast<float4*>(s_sum)[c4] = a;
        reinterpret_cast<float4*>(s_max)[c4] = mm;
    }
    __syncthreads();

    // Stage 1: hidden = relu(pooled @ w1). Threads 0..63 -> sum branch, 64..127 -> max branch.
    if (tid < 128) {
        const int j = tid & 63;
        const float* src = (tid < 64) ? s_sum : s_max;
        float acc = 0.f;
        #pragma unroll 8
        for (int k = 0; k < CCH; k++)
            acc = fmaf(src[k], w1[k * HID + j], acc);
        s_h[tid] = fmaxf(acc, 0.f);
    }
    __syncthreads();

    // Stage 2: y = relu((h_sum + h_max) @ w2). All 256 threads, one output channel each.
    {
        float acc = 0.f;
        #pragma unroll 8
        for (int j = 0; j < HID; j++)
            acc = fmaf(s_h[j] + s_h[HID + j], w2[j * CCH + tid], acc);
        g_y[b * CCH + tid] = fmaxf(acc, 0.f);
    }
}

// ---------------------------------------------------------------------------
// Kernel 3: gather-gate: out[i,c] = x[i,c] * y[batch[i], c]. Pure streaming.
// ---------------------------------------------------------------------------
__global__ void __launch_bounds__(256) gate_kernel(
    const float4* __restrict__ x4,
    const int*    __restrict__ b32,
    float4*       __restrict__ out4,
    int n)
{
    long long i = (long long)blockIdx.x * blockDim.x + threadIdx.x;
    long long total = (long long)n * C4;
    if (i >= total) return;

    bool is64 = (b32[n - 1] == 0);   // uniform broadcast load, L1-hot
    int row = (int)(i >> 6);
    int c4  = (int)(i & 63);
    int b   = load_batch(b32, is64, row);

    float4 xv = x4[i];
    float4 yv = reinterpret_cast<const float4*>(g_y)[b * C4 + c4];
    out4[i] = make_float4(xv.x * yv.x, xv.y * yv.y, xv.z * yv.z, xv.w * yv.w);
}

// ---------------------------------------------------------------------------
extern "C" void kernel_launch(void* const* d_in, const int* in_sizes, int n_in,
                              void* d_out, int out_size) {
    // metadata order: x [N*C] f32, batch [N] int, w1 [C*H] f32, w2 [H*C] f32
    const float* x     = (const float*)d_in[0];
    const int*   batch = (const int*)d_in[1];
    const float* w1    = (const float*)d_in[2];
    const float* w2    = (const float*)d_in[3];
    const int n = in_sizes[1];

    seg_bounds_kernel<<<(BSEG + 1 + 255) / 256, 256>>>(batch, n);
    seg_reduce_mlp_kernel<<<BSEG, 256>>>((const float4*)x, w1, w2);

    long long total = (long long)n * C4;
    int blocks = (int)((total + 255) / 256);
    gate_kernel<<<blocks, 256>>>((const float4*)x, batch, (float4*)d_out, n);
}